// round 15
// baseline (speedup 1.0000x reference)
#include <cuda_runtime.h>
#include <cstdint>

// x: (8, 32, 32, 32, 32) f32   -> d_in[0]
// W: (32, 16, 3, 3, 3)   f32   -> d_in[1]
// b: (16,)               f32   -> d_in[2]
// out: (8, 1, 10, 10, 10) f32  -> d_out (8000 elements)

#define NG16      500         // groups of 16 cells
#define THREADS   512
#define GRID_BLKS 152

// smem layout (floats):
//   Ws : [0, 13952)                 W as [ci][k][co], ci stride 436 floats
//                                   (109 float4 -> odd stride spreads banks)
//   xs : [13952, +32768)            4 quads x [ci][slot][cell4] float4
//   red: +512   cb: +16   ctr: +1
#define WS_OFF   0
#define WS_CI_F4 109
#define XS_OFF   13952
#define RED_OFF  (XS_OFF + 32768)
#define CB_OFF   (RED_OFF + 512)
#define SMEM_FLOATS (CB_OFF + 16 + 8)
#define SMEM_BYTES  (SMEM_FLOATS * 4)

__device__ unsigned g_ctr;

__device__ __forceinline__ unsigned long long pack2(float v) {
    unsigned long long r;
    asm("mov.b64 %0, {%1, %1};" : "=l"(r) : "f"(v));
    return r;
}
__device__ __forceinline__ unsigned long long pk64(float lo, float hi) {
    unsigned long long r;
    asm("mov.b64 %0, {%1, %2};" : "=l"(r) : "f"(lo), "f"(hi));
    return r;
}
__device__ __forceinline__ void fma2(unsigned long long& d,
                                     unsigned long long a,
                                     unsigned long long b) {
    asm("fma.rn.f32x2 %0, %1, %2, %0;" : "+l"(d) : "l"(a), "l"(b));
}
__device__ __forceinline__ void unpack2(unsigned long long v, float& lo, float& hi) {
    asm("mov.b64 {%0, %1}, %2;" : "=f"(lo), "=f"(hi) : "l"(v));
}

// Bank-balanced slot permutation for the 4x4x4 x-window (validated in R13).
__device__ __forceinline__ int xslot(int d, int h, int w) {
    int k  = (d + 2 * h + 5 * w) & 7;
    int r2 = (k >= 2) ? (h & 1) : (d >> 1);
    return k + 8 * ((w << 1) + r2);
}

extern "C" __global__ void __launch_bounds__(THREADS, 1)
fused_ct3d_pool_kernel(const float* __restrict__ x,
                       const float* __restrict__ W,
                       const float* __restrict__ b,
                       float* __restrict__ out)
{
    extern __shared__ float smem[];
    float*  Ws  = smem + WS_OFF;
    float4* xs4 = reinterpret_cast<float4*>(smem + XS_OFF);
    float*  red = smem + RED_OFF;
    int*    cb  = (int*)(smem + CB_OFF);
    unsigned* ctr_bc = (unsigned*)(smem + CB_OFF + 16);
    const float4* wf4 = reinterpret_cast<const float4*>(Ws);

    const int tid = threadIdx.x;

    // ---- Stage W once per block: global [ci][co][k] -> smem [ci][k][co],
    //      ci stride padded to 436 floats (109 float4) ----
    for (int i = tid; i < 13824; i += THREADS) {
        int ci = i / 432;
        int r  = i - ci * 432;
        int co = r / 27;
        int k  = r - co * 27;
        Ws[ci * 436 + k * 16 + co] = W[i];
    }
    float bsum = 0.f;
    #pragma unroll
    for (int i = 0; i < 16; i++) bsum += b[i];

    const int warp = tid >> 5;       // 0..15
    const int lane = tid & 31;
    const int quad = warp >> 2;      // 0..3 : cell-quad within group of 16
    const int role = (warp >> 1) & 1;// 0 = {7,3,1} (14 units), 1 = {6,5,4,2,0} (13)
    const int half = warp & 1;       // co-half: co 8*half .. 8*half+7

    // lane -> position within a 3x3x3 parity class (lanes 27..31 dup q=26)
    const int q  = (lane < 27) ? lane : 26;
    const int a  = q / 9;
    const int bq = (q - a * 9) / 3;
    const int c  = q - a * 9 - bq * 3;

    const float4* xq = xs4 + quad * 2048;

    // cooperative weight-chunk load index pieces (per-lane constants)
    const int wlane_ci   = lane >> 1;   // which ci within the 16-chunk
    const int wlane_part = lane & 1;    // 0 -> co 0-3 of half, 1 -> co 4-7

    // staging decomposition of tid
    const int s_ci = tid >> 4;
    const int s_d  = (tid >> 2) & 3;
    const int s_h  = tid & 3;

    while (true) {
        __syncthreads();            // previous iteration fully consumed
        if (tid == 0) *ctr_bc = atomicAdd(&g_ctr, 1u);
        __syncthreads();
        const unsigned g = *ctr_bc;
        if (g >= NG16) break;

        // ---- per-cell gmem base offsets ----
        if (tid < 16) {
            const int cell = g * 16 + tid;
            const int n  = cell / 1000;
            const int r3 = cell - n * 1000;
            const int pz = r3 / 100;
            const int py = (r3 / 10) % 10;
            const int px = r3 % 10;
            cb[tid] = n * 32 * 32768 + 3 * pz * 1024 + 3 * py * 32 + 3 * px;
        }
        __syncthreads();

        // ---- Stage 4 quads ----
        #pragma unroll 1
        for (int qq = 0; qq < 4; qq++) {
            float v[4][4];
            #pragma unroll
            for (int cc = 0; cc < 4; cc++) {
                const float* src = x + cb[qq * 4 + cc] + s_ci * 32768 + s_d * 1024 + s_h * 32;
                v[cc][0] = src[0]; v[cc][1] = src[1]; v[cc][2] = src[2]; v[cc][3] = src[3];
            }
            float4* dst = xs4 + qq * 2048 + s_ci * 64;
            #pragma unroll
            for (int w = 0; w < 4; w++) {
                float4 o;
                o.x = v[0][w]; o.y = v[1][w]; o.z = v[2][w]; o.w = v[3][w];
                dst[xslot(s_d, s_h, w)] = o;
            }
        }
        __syncthreads();

        // ---- Compute: warp = (quad, role, half); 4 cells, 8 co ----
        float cmax[4][8];
        #pragma unroll
        for (int cc = 0; cc < 4; cc++)
            #pragma unroll
            for (int i = 0; i < 8; i++) cmax[cc][i] = -3.402823466e38f;

        const int ncls = role ? 5 : 3;
        #pragma unroll 1
        for (int ic = 0; ic < ncls; ic++) {
            int cls;
            if (role) { const int lb[5] = {6, 5, 4, 2, 0}; cls = lb[ic]; }
            else      { const int la[3] = {7, 3, 1};       cls = la[ic]; }
            const int pd = (cls >> 2) & 1;
            const int ph = (cls >> 1) & 1;
            const int pw = cls & 1;

            unsigned long long acc[4][4];
            #pragma unroll
            for (int cc = 0; cc < 4; cc++)
                #pragma unroll
                for (int i = 0; i < 4; i++) acc[cc][i] = 0ull;

            const int nd = pd + 1, nh = ph + 1, nw = pw + 1;
            #pragma unroll 1
            for (int td = 0; td < nd; td++) {
                const int kd = pd ? (2 * td)     : 1;
                const int rd = pd ? (a + 1 - td) : a;
                #pragma unroll 1
                for (int th2 = 0; th2 < nh; th2++) {
                    const int kh = ph ? (2 * th2)      : 1;
                    const int rh = ph ? (bq + 1 - th2) : bq;
                    #pragma unroll 1
                    for (int tw2 = 0; tw2 < nw; tw2++) {
                        const int kw = pw ? (2 * tw2)   : 1;
                        const int rw = pw ? (c + 1 - tw2) : c;
                        const int k  = (kd * 3 + kh) * 3 + kw;
                        const float4* xp = xq + xslot(rd, rh, rw);
                        const int wbase = k * 4 + half * 2 + wlane_part;

                        #pragma unroll
                        for (int ch = 0; ch < 2; ch++) {
                            const int ci0 = ch * 16;
                            // cooperative chunk load: 16 ci x 32B in ONE LDS.128
                            float4 wreg = wf4[(ci0 + wlane_ci) * WS_CI_F4 + wbase];
                            #pragma unroll 4
                            for (int j = 0; j < 16; j++) {
                                const int s0 = 2 * j, s1 = 2 * j + 1;
                                float a0 = __shfl_sync(0xffffffffu, wreg.x, s0);
                                float a1 = __shfl_sync(0xffffffffu, wreg.y, s0);
                                float a2 = __shfl_sync(0xffffffffu, wreg.z, s0);
                                float a3 = __shfl_sync(0xffffffffu, wreg.w, s0);
                                float b0 = __shfl_sync(0xffffffffu, wreg.x, s1);
                                float b1 = __shfl_sync(0xffffffffu, wreg.y, s1);
                                float b2 = __shfl_sync(0xffffffffu, wreg.z, s1);
                                float b3 = __shfl_sync(0xffffffffu, wreg.w, s1);
                                unsigned long long wAx = pk64(a0, a1);
                                unsigned long long wAy = pk64(a2, a3);
                                unsigned long long wBx = pk64(b0, b1);
                                unsigned long long wBy = pk64(b2, b3);
                                float4 xv = xp[(ci0 + j) * 64];
                                unsigned long long xx0 = pack2(xv.x);
                                unsigned long long xx1 = pack2(xv.y);
                                unsigned long long xx2 = pack2(xv.z);
                                unsigned long long xx3 = pack2(xv.w);
                                fma2(acc[0][0], xx0, wAx); fma2(acc[0][1], xx0, wAy);
                                fma2(acc[0][2], xx0, wBx); fma2(acc[0][3], xx0, wBy);
                                fma2(acc[1][0], xx1, wAx); fma2(acc[1][1], xx1, wAy);
                                fma2(acc[1][2], xx1, wBx); fma2(acc[1][3], xx1, wBy);
                                fma2(acc[2][0], xx2, wAx); fma2(acc[2][1], xx2, wAy);
                                fma2(acc[2][2], xx2, wBx); fma2(acc[2][3], xx2, wBy);
                                fma2(acc[3][0], xx3, wAx); fma2(acc[3][1], xx3, wAy);
                                fma2(acc[3][2], xx3, wBx); fma2(acc[3][3], xx3, wBy);
                            }
                        }
                    }
                }
            }
            #pragma unroll
            for (int cc = 0; cc < 4; cc++)
                #pragma unroll
                for (int i = 0; i < 4; i++) {
                    float lo, hi;
                    unpack2(acc[cc][i], lo, hi);
                    cmax[cc][2 * i]     = fmaxf(cmax[cc][2 * i], lo);
                    cmax[cc][2 * i + 1] = fmaxf(cmax[cc][2 * i + 1], hi);
                }
        }

        // ---- per-warp butterfly max over positions ----
        #pragma unroll
        for (int cc = 0; cc < 4; cc++)
            #pragma unroll
            for (int i = 0; i < 8; i++) {
                #pragma unroll
                for (int off = 16; off; off >>= 1)
                    cmax[cc][i] = fmaxf(cmax[cc][i],
                                        __shfl_xor_sync(0xffffffffu, cmax[cc][i], off));
            }
        if (lane == 0) {
            #pragma unroll
            for (int cc = 0; cc < 4; cc++)
                #pragma unroll
                for (int i = 0; i < 8; i++)
                    red[warp * 32 + cc * 8 + i] = cmax[cc][i];
        }
        __syncthreads();

        // ---- combine roles per (cell, co), sum over co, write out ----
        if (tid < 16) {
            const int qd = tid >> 2;      // quad
            const int cc = tid & 3;       // cell within quad
            float t = 0.f;
            #pragma unroll
            for (int hf = 0; hf < 2; hf++)
                #pragma unroll
                for (int i = 0; i < 8; i++) {
                    const float vA = red[(qd * 4 + 0 * 2 + hf) * 32 + cc * 8 + i];
                    const float vB = red[(qd * 4 + 1 * 2 + hf) * 32 + cc * 8 + i];
                    t += fmaxf(vA, vB);
                }
            out[g * 16 + tid] = t + bsum;
        }
    }
}

extern "C" void kernel_launch(void* const* d_in, const int* in_sizes, int n_in,
                              void* d_out, int out_size)
{
    const float* x = (const float*)d_in[0];
    const float* W = (const float*)d_in[1];
    const float* b = (const float*)d_in[2];
    float* out = (float*)d_out;

    // reset work-stealing counter
    void* ctr_addr = nullptr;
    cudaGetSymbolAddress(&ctr_addr, g_ctr);
    cudaMemsetAsync(ctr_addr, 0, sizeof(unsigned));

    cudaFuncSetAttribute(fused_ct3d_pool_kernel,
                         cudaFuncAttributeMaxDynamicSharedMemorySize, SMEM_BYTES);
    fused_ct3d_pool_kernel<<<GRID_BLKS, THREADS, SMEM_BYTES>>>(x, W, b, out);
}

// round 17
// speedup vs baseline: 1.3126x; 1.3126x over previous
#include <cuda_runtime.h>
#include <cstdint>

// x: (8, 32, 32, 32, 32) f32   -> d_in[0]
// W: (32, 16, 3, 3, 3)   f32   -> d_in[1]
// b: (16,)               f32   -> d_in[2]
// out: (8, 1, 10, 10, 10) f32  -> d_out (8000 elements)

#define NG16      500         // groups of 16 cells
#define THREADS   256
#define GRID_BLKS 152

// smem layout (floats):
//   Ws : [0, 13824)           W as [ci][k][co]  (ci*432 + k*16 + co)
//   xs : [13824, +32768)      4 quads x [ci][slot][cell4] float4
//   cm : [46592, +8704)       8 warps x 16 lanes x (8 cell x 8 co), lane
//                             stride 68 floats (17 float4, +1 pad)
//   cb : [55296, +16)         per-cell gmem base offsets (int)
//   ctr broadcast uint after cb
#define WS_OFF   0
#define XS_OFF   13824
#define CM_OFF   (XS_OFF + 32768)        // 46592
#define CM_WARP  1088                    // 16 lanes * 68 floats
#define CB_OFF   (CM_OFF + 8 * CM_WARP)  // 55296
#define SMEM_FLOATS (CB_OFF + 16 + 8)
#define SMEM_BYTES  (SMEM_FLOATS * 4)

__device__ unsigned g_ctr;

__device__ __forceinline__ unsigned long long pack2(float v) {
    unsigned long long r;
    asm("mov.b64 %0, {%1, %1};" : "=l"(r) : "f"(v));
    return r;
}
__device__ __forceinline__ void fma2(unsigned long long& d,
                                     unsigned long long a,
                                     unsigned long long b) {
    asm("fma.rn.f32x2 %0, %1, %2, %0;" : "+l"(d) : "l"(a), "l"(b));
}
__device__ __forceinline__ void unpack2(unsigned long long v, float& lo, float& hi) {
    asm("mov.b64 {%0, %1}, %2;" : "=f"(lo), "=f"(hi) : "l"(v));
}

// Bank-balanced slot permutation for the 4x4x4 x-window (validated in R13).
__device__ __forceinline__ int xslot(int d, int h, int w) {
    int k  = (d + 2 * h + 5 * w) & 7;
    int r2 = (k >= 2) ? (h & 1) : (d >> 1);
    return k + 8 * ((w << 1) + r2);
}

extern "C" __global__ void __launch_bounds__(THREADS, 1)
fused_ct3d_pool_kernel(const float* __restrict__ x,
                       const float* __restrict__ W,
                       const float* __restrict__ b,
                       float* __restrict__ out)
{
    extern __shared__ float smem[];
    float*  Ws  = smem + WS_OFF;
    float4* xs4 = reinterpret_cast<float4*>(smem + XS_OFF);
    float*  cms = smem + CM_OFF;
    int*    cb  = (int*)(smem + CB_OFF);
    unsigned* ctr_bc = (unsigned*)(smem + CB_OFF + 16);

    const int tid = threadIdx.x;

    // ---- Stage W once per block: global [ci][co][k] -> smem [ci][k][co] ----
    for (int i = tid; i < 13824; i += THREADS) {
        int ci = i / 432;
        int r  = i - ci * 432;
        int co = r / 27;
        int k  = r - co * 27;
        Ws[ci * 432 + k * 16 + co] = W[i];
    }
    float bsum = 0.f;
    #pragma unroll
    for (int i = 0; i < 16; i++) bsum += b[i];

    const int warp = tid >> 5;       // 0..7
    const int lane = tid & 31;
    const int oct  = warp >> 2;      // 0..1 : 8-cell half of the 16-cell group
    const int role = (warp >> 1) & 1;// 0 = {7,3,1} (14 units), 1 = {6,5,4,2,0} (13)
    const int half = warp & 1;       // co-half: co 8*half .. 8*half+7

    // lane -> position within a 3x3x3 parity class (lanes 27..31 dup q=26)
    const int q  = (lane < 27) ? lane : 26;
    const int a  = q / 9;
    const int bq = (q - a * 9) / 3;
    const int c  = q - a * 9 - bq * 3;

    const float4* xq0 = xs4 + (oct * 2) * 2048;      // quad A of this oct
    const float4* xq1 = xq0 + 2048;                  // quad B
    float4* cm4 = reinterpret_cast<float4*>(cms + warp * CM_WARP) + (lane & 15) * 17;

    // staging decomposition of tid (256 thr -> 2 ci passes)
    const int s_ci = tid >> 4;       // 0..15
    const int s_d  = (tid >> 2) & 3;
    const int s_h  = tid & 3;

    while (true) {
        __syncthreads();            // previous iteration fully consumed
        if (tid == 0) *ctr_bc = atomicAdd(&g_ctr, 1u);
        __syncthreads();
        const unsigned g = *ctr_bc;
        if (g >= NG16) break;

        // ---- per-cell gmem base offsets + cmax init ----
        if (tid < 16) {
            const int cell = g * 16 + tid;
            const int n  = cell / 1000;
            const int r3 = cell - n * 1000;
            const int pz = r3 / 100;
            const int py = (r3 / 10) % 10;
            const int px = r3 % 10;
            cb[tid] = n * 32 * 32768 + 3 * pz * 1024 + 3 * py * 32 + 3 * px;
        }
        for (int i = tid; i < 8 * CM_WARP; i += THREADS)
            cms[i] = -3.402823466e38f;
        __syncthreads();

        // ---- Stage 4 quads (2 ci-passes with 256 threads) ----
        #pragma unroll 1
        for (int it = 0; it < 2; it++) {
            const int ci = s_ci + 16 * it;
            #pragma unroll 1
            for (int qq = 0; qq < 4; qq++) {
                float v[4][4];
                #pragma unroll
                for (int cc = 0; cc < 4; cc++) {
                    const float* src = x + cb[qq * 4 + cc] + ci * 32768 + s_d * 1024 + s_h * 32;
                    v[cc][0] = src[0]; v[cc][1] = src[1]; v[cc][2] = src[2]; v[cc][3] = src[3];
                }
                float4* dst = xs4 + qq * 2048 + ci * 64;
                #pragma unroll
                for (int w = 0; w < 4; w++) {
                    float4 o;
                    o.x = v[0][w]; o.y = v[1][w]; o.z = v[2][w]; o.w = v[3][w];
                    dst[xslot(s_d, s_h, w)] = o;
                }
            }
        }
        __syncthreads();

        // ---- Compute: warp = (oct, role, half); 8 cells, 8 co ----
        const int ncls = role ? 5 : 3;
        #pragma unroll 1
        for (int ic = 0; ic < ncls; ic++) {
            int cls;
            if (role) { const int lb[5] = {6, 5, 4, 2, 0}; cls = lb[ic]; }
            else      { const int la[3] = {7, 3, 1};       cls = la[ic]; }
            const int pd = (cls >> 2) & 1;
            const int ph = (cls >> 1) & 1;
            const int pw = cls & 1;

            unsigned long long acc[8][4];
            #pragma unroll
            for (int cc = 0; cc < 8; cc++)
                #pragma unroll
                for (int i = 0; i < 4; i++) acc[cc][i] = 0ull;

            const int nd = pd + 1, nh = ph + 1, nw = pw + 1;
            #pragma unroll 1
            for (int td = 0; td < nd; td++) {
                const int kd = pd ? (2 * td)     : 1;
                const int rd = pd ? (a + 1 - td) : a;
                #pragma unroll 1
                for (int th2 = 0; th2 < nh; th2++) {
                    const int kh = ph ? (2 * th2)      : 1;
                    const int rh = ph ? (bq + 1 - th2) : bq;
                    #pragma unroll 1
                    for (int tw2 = 0; tw2 < nw; tw2++) {
                        const int kw = pw ? (2 * tw2)   : 1;
                        const int rw = pw ? (c + 1 - tw2) : c;
                        const int k  = (kd * 3 + kh) * 3 + kw;
                        const int so = xslot(rd, rh, rw);
                        const float4* xp0 = xq0 + so;
                        const float4* xp1 = xq1 + so;
                        const ulonglong2* wp =
                            reinterpret_cast<const ulonglong2*>(Ws) + k * 4 + half * 2;
                        #pragma unroll 4
                        for (int ci = 0; ci < 32; ci++) {
                            float4 xa = xp0[ci * 64];
                            float4 xb = xp1[ci * 64];
                            ulonglong2 wA = wp[ci * 108 + 0];
                            ulonglong2 wB = wp[ci * 108 + 1];
                            unsigned long long a0 = pack2(xa.x);
                            unsigned long long a1 = pack2(xa.y);
                            unsigned long long a2 = pack2(xa.z);
                            unsigned long long a3 = pack2(xa.w);
                            unsigned long long b0 = pack2(xb.x);
                            unsigned long long b1 = pack2(xb.y);
                            unsigned long long b2 = pack2(xb.z);
                            unsigned long long b3 = pack2(xb.w);
                            fma2(acc[0][0], a0, wA.x); fma2(acc[0][1], a0, wA.y);
                            fma2(acc[0][2], a0, wB.x); fma2(acc[0][3], a0, wB.y);
                            fma2(acc[1][0], a1, wA.x); fma2(acc[1][1], a1, wA.y);
                            fma2(acc[1][2], a1, wB.x); fma2(acc[1][3], a1, wB.y);
                            fma2(acc[2][0], a2, wA.x); fma2(acc[2][1], a2, wA.y);
                            fma2(acc[2][2], a2, wB.x); fma2(acc[2][3], a2, wB.y);
                            fma2(acc[3][0], a3, wA.x); fma2(acc[3][1], a3, wA.y);
                            fma2(acc[3][2], a3, wB.x); fma2(acc[3][3], a3, wB.y);
                            fma2(acc[4][0], b0, wA.x); fma2(acc[4][1], b0, wA.y);
                            fma2(acc[4][2], b0, wB.x); fma2(acc[4][3], b0, wB.y);
                            fma2(acc[5][0], b1, wA.x); fma2(acc[5][1], b1, wA.y);
                            fma2(acc[5][2], b1, wB.x); fma2(acc[5][3], b1, wB.y);
                            fma2(acc[6][0], b2, wA.x); fma2(acc[6][1], b2, wA.y);
                            fma2(acc[6][2], b2, wB.x); fma2(acc[6][3], b2, wB.y);
                            fma2(acc[7][0], b3, wA.x); fma2(acc[7][1], b3, wA.y);
                            fma2(acc[7][2], b3, wB.x); fma2(acc[7][3], b3, wB.y);
                        }
                    }
                }
            }

            // ---- class-end fold: 1-stage lane fold (l vs l+16), RMW smem cmax ----
            #pragma unroll
            for (int cc = 0; cc < 8; cc++) {
                float v[8];
                #pragma unroll
                for (int i = 0; i < 4; i++) {
                    float lo, hi;
                    unpack2(acc[cc][i], lo, hi);
                    float lo2 = __shfl_xor_sync(0xffffffffu, lo, 16);
                    float hi2 = __shfl_xor_sync(0xffffffffu, hi, 16);
                    v[2 * i]     = fmaxf(lo, lo2);
                    v[2 * i + 1] = fmaxf(hi, hi2);
                }
                if (lane < 16) {
                    float4 o0 = cm4[cc * 2 + 0];
                    float4 o1 = cm4[cc * 2 + 1];
                    o0.x = fmaxf(o0.x, v[0]); o0.y = fmaxf(o0.y, v[1]);
                    o0.z = fmaxf(o0.z, v[2]); o0.w = fmaxf(o0.w, v[3]);
                    o1.x = fmaxf(o1.x, v[4]); o1.y = fmaxf(o1.y, v[5]);
                    o1.z = fmaxf(o1.z, v[6]); o1.w = fmaxf(o1.w, v[7]);
                    cm4[cc * 2 + 0] = o0;
                    cm4[cc * 2 + 1] = o1;
                }
            }
        }
        __syncthreads();

        // ---- final reduction: thread = (cell, co) ----
        {
            const int cell = tid >> 4;        // 0..15
            const int co   = tid & 15;        // 0..15
            const int oc   = cell >> 3;
            const int cin  = cell & 7;
            const int hf   = co >> 3;
            const int coin = co & 7;
            float m = -3.402823466e38f;
            #pragma unroll
            for (int r = 0; r < 2; r++) {
                const float* base = cms + (oc * 4 + r * 2 + hf) * CM_WARP;
                #pragma unroll
                for (int l = 0; l < 16; l++)
                    m = fmaxf(m, base[l * 68 + cin * 8 + coin]);
            }
            // sum over 16 co (shfl within 16-lane co groups)
            #pragma unroll
            for (int off = 8; off; off >>= 1)
                m += __shfl_xor_sync(0xffffffffu, m, off);
            if (co == 0)
                out[g * 16 + cell] = m + bsum;
        }
    }
}

extern "C" void kernel_launch(void* const* d_in, const int* in_sizes, int n_in,
                              void* d_out, int out_size)
{
    const float* x = (const float*)d_in[0];
    const float* W = (const float*)d_in[1];
    const float* b = (const float*)d_in[2];
    float* out = (float*)d_out;

    // reset work-stealing counter
    void* ctr_addr = nullptr;
    cudaGetSymbolAddress(&ctr_addr, g_ctr);
    cudaMemsetAsync(ctr_addr, 0, sizeof(unsigned));

    cudaFuncSetAttribute(fused_ct3d_pool_kernel,
                         cudaFuncAttributeMaxDynamicSharedMemorySize, SMEM_BYTES);
    fused_ct3d_pool_kernel<<<GRID_BLKS, THREADS, SMEM_BYTES>>>(x, W, b, out);
}